// round 1
// baseline (speedup 1.0000x reference)
#include <cuda_runtime.h>
#include <math.h>

#define B_   4
#define N_   8192
#define DIM_ 512
#define H_   8
#define DH_  64
#define BH_  (B_*H_)          // 32
#define MROWS (B_*N_)         // 32768
#define QKVN  (3*DIM_)        // 1536

// ---------------- scratch (device globals; no allocs allowed) ----------------
__device__ float g_q[BH_*N_*DH_];      // 64 MB, [bh][n][d]
__device__ float g_k[BH_*N_*DH_];      // 64 MB
__device__ float g_v[BH_*N_*DH_];      // 64 MB
__device__ float g_attn[MROWS*DIM_];   // 64 MB, [b*n][h*64+e]
__device__ float g_ctx[BH_*DH_*DH_];   // [bh][d][e]
__device__ float g_ksum[BH_*DH_];      // [bh][d]
__device__ int   g_maskflags[2];       // [0]: f32 signature, [1]: nonzero at off%4!=0

// =============================================================================
// GEMM1: qkv = X[32768,512] @ Wqkv[512,1536], scatter into g_q/g_k/g_v
// 128x128 tile, BK=16, 256 threads, 8x8 per thread
// =============================================================================
__global__ __launch_bounds__(256) void gemm_qkv_kernel(const float* __restrict__ X,
                                                       const float* __restrict__ W) {
    const int KD = DIM_, NW = QKVN;
    __shared__ float As[16][132];   // padded: transposed A stores
    __shared__ float Bs[16][128];

    const int tid   = threadIdx.x;
    const int mBase = blockIdx.y * 128;
    const int nBase = blockIdx.x * 128;

    const int aRow = tid >> 2;           // 0..63
    const int aCol = (tid & 3) << 2;     // 0,4,8,12
    const int bRow = tid >> 5;           // 0..7
    const int bCol = (tid & 31) << 2;    // 0..124

    const int ty = tid >> 4, tx = tid & 15;
    const int m0 = ty * 8,  n0 = tx * 8;

    float acc[8][8];
    #pragma unroll
    for (int i = 0; i < 8; ++i)
        #pragma unroll
        for (int j = 0; j < 8; ++j) acc[i][j] = 0.f;

    for (int k0 = 0; k0 < KD; k0 += 16) {
        #pragma unroll
        for (int rr = 0; rr < 128; rr += 64) {
            float4 v = *(const float4*)&X[(size_t)(mBase + aRow + rr) * KD + k0 + aCol];
            As[aCol+0][aRow+rr] = v.x;
            As[aCol+1][aRow+rr] = v.y;
            As[aCol+2][aRow+rr] = v.z;
            As[aCol+3][aRow+rr] = v.w;
        }
        #pragma unroll
        for (int rr = 0; rr < 16; rr += 8) {
            *(float4*)&Bs[bRow+rr][bCol] =
                *(const float4*)&W[(size_t)(k0 + bRow + rr) * NW + nBase + bCol];
        }
        __syncthreads();

        #pragma unroll
        for (int kk = 0; kk < 16; ++kk) {
            float4 a0 = *(float4*)&As[kk][m0];
            float4 a1 = *(float4*)&As[kk][m0+4];
            float4 b0 = *(float4*)&Bs[kk][n0];
            float4 b1 = *(float4*)&Bs[kk][n0+4];
            float ar[8] = {a0.x,a0.y,a0.z,a0.w,a1.x,a1.y,a1.z,a1.w};
            float br[8] = {b0.x,b0.y,b0.z,b0.w,b1.x,b1.y,b1.z,b1.w};
            #pragma unroll
            for (int i = 0; i < 8; ++i)
                #pragma unroll
                for (int j = 0; j < 8; ++j)
                    acc[i][j] += ar[i] * br[j];
        }
        __syncthreads();
    }

    // scatter epilogue: col c in [0,1536): part=c/512, h=(c%512)/64, d=c%64
    const int part    = nBase >> 9;            // constant per block
    const int rembase = nBase & 511;
    float* dstbuf = (part == 0) ? g_q : ((part == 1) ? g_k : g_v);

    #pragma unroll
    for (int i = 0; i < 8; ++i) {
        int gm = mBase + m0 + i;
        int b  = gm >> 13;
        int n  = gm & (N_-1);
        #pragma unroll
        for (int j = 0; j < 8; ++j) {
            int rem = rembase + n0 + j;
            int h = rem >> 6, d = rem & 63;
            dstbuf[(size_t)(((b << 3) + h) * N_ + n) * DH_ + d] = acc[i][j];
        }
    }
}

// =============================================================================
// q softmax over feature dim d=64 (after *SCALE). One warp per row.
// =============================================================================
__global__ __launch_bounds__(256) void qsoftmax_kernel() {
    const float SCALE = 0.125f;  // DH^-0.5
    int gwarp = (blockIdx.x * 256 + threadIdx.x) >> 5;   // row id, exact grid
    int lane  = threadIdx.x & 31;
    float2 v = *(const float2*)&g_q[(size_t)gwarp * 64 + lane * 2];
    float a = v.x * SCALE, b = v.y * SCALE;
    float mx = fmaxf(a, b);
    #pragma unroll
    for (int off = 16; off > 0; off >>= 1)
        mx = fmaxf(mx, __shfl_xor_sync(0xffffffff, mx, off));
    float ea = __expf(a - mx), eb = __expf(b - mx);
    float s = ea + eb;
    #pragma unroll
    for (int off = 16; off > 0; off >>= 1)
        s += __shfl_xor_sync(0xffffffff, s, off);
    float inv = 1.f / s;
    float2 o = make_float2(ea * inv, eb * inv);
    *(float2*)&g_q[(size_t)gwarp * 64 + lane * 2] = o;
}

// =============================================================================
// k softmax over n: pass 1 — partial sums of exp(k) per (bh,d) column.
// grid (32 bh, 8 chunks), 256 threads: d = t&63, group g = t>>6 covers 256 n's.
// =============================================================================
__global__ __launch_bounds__(256) void ksum_kernel() {
    int bh = blockIdx.x, chunk = blockIdx.y;
    int t = threadIdx.x;
    int d = t & 63, g = t >> 6;
    const float* kp = g_k + (size_t)bh * N_ * DH_;
    int nb = chunk * 1024 + g * 256;
    float s = 0.f;
    #pragma unroll 8
    for (int i = 0; i < 256; ++i)
        s += __expf(kp[(size_t)(nb + i) * DH_ + d]);
    __shared__ float red[4][64];
    red[g][d] = s;
    __syncthreads();
    if (g == 0)
        atomicAdd(&g_ksum[bh * DH_ + d], red[0][d] + red[1][d] + red[2][d] + red[3][d]);
}

// =============================================================================
// Mask dtype detection (bool may be serialized as u8 / i32 / f32).
// 65536 threads, each inspects 4 consecutive bytes.
// =============================================================================
__global__ __launch_bounds__(256) void detect_mask_kernel(const unsigned char* __restrict__ m) {
    int i = blockIdx.x * 256 + threadIdx.x;        // 0..65535
    uchar4 v = ((const uchar4*)m)[i];
    bool f32sig = (v.w == 0x3f);                   // high byte of 1.0f at off%4==3
    bool offnz  = (v.y | v.z | v.w) != 0;          // nonzero off-bytes -> u8 layout
    unsigned b1 = __ballot_sync(0xffffffff, f32sig);
    unsigned b2 = __ballot_sync(0xffffffff, offnz);
    if ((threadIdx.x & 31) == 0) {
        if (b1) atomicOr(&g_maskflags[0], 1);
        if (b2) atomicOr(&g_maskflags[1], 1);
    }
}

// =============================================================================
// k softmax pass 2: k = mask ? 0 : exp(k)/sum.  Vectorized float4 over d.
// =============================================================================
__global__ __launch_bounds__(256) void knorm_kernel(const void* __restrict__ mask) {
    int i4  = blockIdx.x * 256 + threadIdx.x;      // 0..4M-1, exact
    int idx = i4 << 2;
    int row = idx >> 6;            // bh*8192 + n
    int d   = idx & 63;
    int bh  = row >> 13;

    int f32f = g_maskflags[0], u8f = g_maskflags[1];
    bool mz;
    if (f32f)      mz = ((const float*)mask)[row] != 0.f;
    else if (u8f)  mz = ((const unsigned char*)mask)[row] != 0;
    else           mz = ((const int*)mask)[row] != 0;

    float4 kv = *(const float4*)&g_k[idx];
    float4 o;
    if (mz) {
        o = make_float4(0.f, 0.f, 0.f, 0.f);
    } else {
        float4 sv = *(const float4*)&g_ksum[(bh << 6) + d];
        o.x = __expf(kv.x) / sv.x;
        o.y = __expf(kv.y) / sv.y;
        o.z = __expf(kv.z) / sv.z;
        o.w = __expf(kv.w) / sv.w;
    }
    *(float4*)&g_k[idx] = o;
}

// =============================================================================
// context[bh][d][e] += sum_n q[n,d]*k[n,e].  grid (32 bh, 8 n-chunks of 1024).
// 256 threads as 16x16, each 4x4 outputs; smem staging of 32-row tiles.
// =============================================================================
__global__ __launch_bounds__(256) void ctx_kernel() {
    int bh = blockIdx.x, chunk = blockIdx.y;
    __shared__ float qs[32][64];
    __shared__ float ks[32][64];
    int t = threadIdx.x;
    int d0 = (t >> 4) << 2, e0 = (t & 15) << 2;
    int lr = t >> 3, lc = (t & 7) << 3;

    const float* qp = g_q + (size_t)(bh * N_ + chunk * 1024) * DH_;
    const float* kp = g_k + (size_t)(bh * N_ + chunk * 1024) * DH_;

    float acc[4][4];
    #pragma unroll
    for (int i = 0; i < 4; ++i)
        #pragma unroll
        for (int j = 0; j < 4; ++j) acc[i][j] = 0.f;

    for (int it = 0; it < 32; ++it) {
        size_t base = (size_t)it * 32 * 64 + (size_t)lr * 64 + lc;
        *(float4*)&qs[lr][lc]   = *(const float4*)&qp[base];
        *(float4*)&qs[lr][lc+4] = *(const float4*)&qp[base + 4];
        *(float4*)&ks[lr][lc]   = *(const float4*)&kp[base];
        *(float4*)&ks[lr][lc+4] = *(const float4*)&kp[base + 4];
        __syncthreads();
        #pragma unroll
        for (int n = 0; n < 32; ++n) {
            float4 qa = *(float4*)&qs[n][d0];
            float4 ka = *(float4*)&ks[n][e0];
            float qr[4] = {qa.x,qa.y,qa.z,qa.w};
            float kr[4] = {ka.x,ka.y,ka.z,ka.w};
            #pragma unroll
            for (int i = 0; i < 4; ++i)
                #pragma unroll
                for (int j = 0; j < 4; ++j)
                    acc[i][j] += qr[i] * kr[j];
        }
        __syncthreads();
    }
    #pragma unroll
    for (int i = 0; i < 4; ++i)
        #pragma unroll
        for (int j = 0; j < 4; ++j)
            atomicAdd(&g_ctx[bh * 4096 + (d0 + i) * 64 + (e0 + j)], acc[i][j]);
}

// =============================================================================
// out[n,e] = sum_d v[n,d] * ctx[d,e], written to g_attn[b*n][h*64+e].
// grid (32 bh, 128 chunks of 64 rows). 256 threads: r = t>>2, e-quarter.
// =============================================================================
__global__ __launch_bounds__(256) void attn_out_kernel() {
    int bh = blockIdx.x, chunk = blockIdx.y;
    __shared__ float cs[64][64];
    __shared__ float vs[64][64];
    int t = threadIdx.x;

    const float* cp = g_ctx + bh * 4096;
    const float* vp = g_v + (size_t)(bh * N_ + chunk * 64) * DH_;
    #pragma unroll
    for (int u = 0; u < 4; ++u) {
        ((float4*)cs)[u * 256 + t] = ((const float4*)cp)[u * 256 + t];
        ((float4*)vs)[u * 256 + t] = ((const float4*)vp)[u * 256 + t];
    }
    __syncthreads();

    int r = t >> 2;
    int e1 = (t & 3) << 4;
    float acc[16];
    #pragma unroll
    for (int j = 0; j < 16; ++j) acc[j] = 0.f;

    #pragma unroll
    for (int dd = 0; dd < 64; ++dd) {
        float vv = vs[r][dd];
        #pragma unroll
        for (int j = 0; j < 16; ++j)
            acc[j] += vv * cs[dd][e1 + j];
    }

    int b = bh >> 3, h = bh & 7;
    int n = chunk * 64 + r;
    float* dst = &g_attn[(size_t)(b * N_ + n) * DIM_ + h * 64 + e1];
    #pragma unroll
    for (int u = 0; u < 4; ++u)
        *(float4*)&dst[u * 4] = make_float4(acc[u*4+0], acc[u*4+1], acc[u*4+2], acc[u*4+3]);
}

// =============================================================================
// GEMM2: out = g_attn[32768,512] @ Wout[512,512] + bout
// =============================================================================
__global__ __launch_bounds__(256) void gemm_out_kernel(const float* __restrict__ W,
                                                       const float* __restrict__ bias,
                                                       float* __restrict__ out) {
    const int KD = DIM_, NW = DIM_;
    __shared__ float As[16][132];
    __shared__ float Bs[16][128];

    const int tid   = threadIdx.x;
    const int mBase = blockIdx.y * 128;
    const int nBase = blockIdx.x * 128;

    const int aRow = tid >> 2;
    const int aCol = (tid & 3) << 2;
    const int bRow = tid >> 5;
    const int bCol = (tid & 31) << 2;

    const int ty = tid >> 4, tx = tid & 15;
    const int m0 = ty * 8,  n0 = tx * 8;

    float acc[8][8];
    #pragma unroll
    for (int i = 0; i < 8; ++i)
        #pragma unroll
        for (int j = 0; j < 8; ++j) acc[i][j] = 0.f;

    for (int k0 = 0; k0 < KD; k0 += 16) {
        #pragma unroll
        for (int rr = 0; rr < 128; rr += 64) {
            float4 v = *(const float4*)&g_attn[(size_t)(mBase + aRow + rr) * KD + k0 + aCol];
            As[aCol+0][aRow+rr] = v.x;
            As[aCol+1][aRow+rr] = v.y;
            As[aCol+2][aRow+rr] = v.z;
            As[aCol+3][aRow+rr] = v.w;
        }
        #pragma unroll
        for (int rr = 0; rr < 16; rr += 8) {
            *(float4*)&Bs[bRow+rr][bCol] =
                *(const float4*)&W[(size_t)(k0 + bRow + rr) * NW + nBase + bCol];
        }
        __syncthreads();

        #pragma unroll
        for (int kk = 0; kk < 16; ++kk) {
            float4 a0 = *(float4*)&As[kk][m0];
            float4 a1 = *(float4*)&As[kk][m0+4];
            float4 b0 = *(float4*)&Bs[kk][n0];
            float4 b1 = *(float4*)&Bs[kk][n0+4];
            float ar[8] = {a0.x,a0.y,a0.z,a0.w,a1.x,a1.y,a1.z,a1.w};
            float br[8] = {b0.x,b0.y,b0.z,b0.w,b1.x,b1.y,b1.z,b1.w};
            #pragma unroll
            for (int i = 0; i < 8; ++i)
                #pragma unroll
                for (int j = 0; j < 8; ++j)
                    acc[i][j] += ar[i] * br[j];
        }
        __syncthreads();
    }

    #pragma unroll
    for (int i = 0; i < 8; ++i) {
        int gm = mBase + m0 + i;
        #pragma unroll
        for (int j = 0; j < 8; j += 4) {
            int gn = nBase + n0 + j;
            float4 bv = *(const float4*)&bias[gn];
            float4 o = make_float4(acc[i][j] + bv.x, acc[i][j+1] + bv.y,
                                   acc[i][j+2] + bv.z, acc[i][j+3] + bv.w);
            *(float4*)&out[(size_t)gm * NW + gn] = o;
        }
    }
}

// =============================================================================
extern "C" void kernel_launch(void* const* d_in, const int* in_sizes, int n_in,
                              void* d_out, int out_size) {
    const float* x    = (const float*)d_in[0];
    const void*  mask = d_in[1];
    const float* Wqkv = (const float*)d_in[2];
    const float* Wout = (const float*)d_in[3];
    const float* bout = (const float*)d_in[4];
    float* out = (float*)d_out;

    void *pks, *pctx, *pfl;
    cudaGetSymbolAddress(&pks,  g_ksum);
    cudaGetSymbolAddress(&pctx, g_ctx);
    cudaGetSymbolAddress(&pfl,  g_maskflags);
    cudaMemsetAsync(pks,  0, sizeof(float) * BH_ * DH_);
    cudaMemsetAsync(pctx, 0, sizeof(float) * BH_ * DH_ * DH_);
    cudaMemsetAsync(pfl,  0, 2 * sizeof(int));

    gemm_qkv_kernel<<<dim3(QKVN / 128, MROWS / 128), 256>>>(x, Wqkv);
    qsoftmax_kernel<<<(BH_ * N_) / 8, 256>>>();                 // 32768 blocks
    ksum_kernel<<<dim3(BH_, 8), 256>>>();
    detect_mask_kernel<<<(BH_ * N_) / 1024, 256>>>((const unsigned char*)mask); // 256 blocks
    knorm_kernel<<<(BH_ * N_ * DH_) / 1024, 256>>>(mask);       // 16384 blocks
    ctx_kernel<<<dim3(BH_, 8), 256>>>();
    attn_out_kernel<<<dim3(BH_, N_ / 64), 256>>>();
    gemm_out_kernel<<<dim3(DIM_ / 128, MROWS / 128), 256>>>(Wout, bout, out);
}